// round 1
// baseline (speedup 1.0000x reference)
#include <cuda_runtime.h>
#include <cstdint>
#include <cstddef>

#define D_MODEL 1024
#define NH      16
#define DH      64
#define BB      4
#define TT      2048
#define BT      (BB * TT)

// Scratch: device globals (no allocation allowed anywhere).
__device__ float g_qkv[(size_t)BT * 3 * D_MODEL];   // [B*T, 3072]
__device__ float g_y  [(size_t)BT * D_MODEL];       // [B*T, 1024]

// ---------------------------------------------------------------------------
// SGEMM: C[M,N] = A[M,K] * B[N,K]^T   (both operands K-contiguous row-major)
// 128x128 block tile, BK=16, 8x8 per thread, 256 threads.
// ---------------------------------------------------------------------------
template<int BM, int BN, int BK, int TM, int TN>
__global__ __launch_bounds__(256)
void sgemm_nt(const float* __restrict__ A, const float* __restrict__ Bw,
              float* __restrict__ C, int M, int N, int K) {
    constexpr int NT = 256;
    __shared__ __align__(16) float As[BK][BM + 4];   // [k][m], pad 4
    __shared__ __align__(16) float Bs[BK][BN + 4];   // [k][n], pad 4

    const int tid = threadIdx.x;
    const int tx  = tid % (BN / TN);   // 0..15
    const int ty  = tid / (BN / TN);   // 0..15
    const int m0  = blockIdx.y * BM;
    const int n0  = blockIdx.x * BN;

    float acc[TM][TN];
    #pragma unroll
    for (int i = 0; i < TM; i++)
        #pragma unroll
        for (int j = 0; j < TN; j++) acc[i][j] = 0.f;

    for (int k0 = 0; k0 < K; k0 += BK) {
        #pragma unroll
        for (int t = 0; t < BM * BK / NT; t++) {
            int e = tid + t * NT;
            int r = e / BK, kk = e % BK;
            As[kk][r] = A[(size_t)(m0 + r) * K + (k0 + kk)];
        }
        #pragma unroll
        for (int t = 0; t < BN * BK / NT; t++) {
            int e = tid + t * NT;
            int r = e / BK, kk = e % BK;
            Bs[kk][r] = Bw[(size_t)(n0 + r) * K + (k0 + kk)];
        }
        __syncthreads();

        #pragma unroll
        for (int kk = 0; kk < BK; kk++) {
            float a[TM], b[TN];
            #pragma unroll
            for (int i = 0; i < TM; i += 4) {
                float4 v = *(const float4*)&As[kk][ty * TM + i];
                a[i] = v.x; a[i+1] = v.y; a[i+2] = v.z; a[i+3] = v.w;
            }
            #pragma unroll
            for (int j = 0; j < TN; j += 4) {
                float4 v = *(const float4*)&Bs[kk][tx * TN + j];
                b[j] = v.x; b[j+1] = v.y; b[j+2] = v.z; b[j+3] = v.w;
            }
            #pragma unroll
            for (int i = 0; i < TM; i++)
                #pragma unroll
                for (int j = 0; j < TN; j++)
                    acc[i][j] += a[i] * b[j];
        }
        __syncthreads();
    }

    #pragma unroll
    for (int i = 0; i < TM; i++) {
        #pragma unroll
        for (int j = 0; j < TN; j += 4) {
            float4 v = make_float4(acc[i][j], acc[i][j+1], acc[i][j+2], acc[i][j+3]);
            *(float4*)&C[(size_t)(m0 + ty * TM + i) * N + (n0 + tx * TN + j)] = v;
        }
    }
}

// ---------------------------------------------------------------------------
// Flash-style causal attention, fp32.
// Block: 256 threads (16x16), 64 queries x 64 keys per tile, Dh=64.
// Smem: Qs[64][64] | KtP[64][65] (K^T, later reused as P) | Vs[64][64]
// ---------------------------------------------------------------------------
#define ATTN_SMEM ((64*64 + 64*65 + 64*64) * 4)

__global__ __launch_bounds__(256)
void attn_flash() {
    extern __shared__ __align__(16) float sm[];
    float* Qs  = sm;                       // [64][64]  row-major [q][d]
    float* KtP = sm + 64 * 64;             // [64][65]  as Kt: [d][key]; as P: [q][key]
    float* Vs  = sm + 64 * 64 + 64 * 65;   // [64][64]  [key][d]

    const int tid = threadIdx.x;
    const int tx  = tid & 15;
    const int ty  = tid >> 4;
    const int qt  = blockIdx.x;      // query tile
    const int h   = blockIdx.y;
    const int b   = blockIdx.z;

    const size_t base = (size_t)b * TT * (3 * D_MODEL);
    const int    hcol = h * DH;

    // Load Q tile
    #pragma unroll
    for (int t = 0; t < 16; t++) {
        int e = tid + t * 256;
        int r = e >> 6, d = e & 63;
        Qs[r * 64 + d] = g_qkv[base + (size_t)(qt * 64 + r) * (3 * D_MODEL) + hcol + d];
    }

    float m_i[4], l_i[4], o[4][4];
    #pragma unroll
    for (int r = 0; r < 4; r++) {
        m_i[r] = -1e30f; l_i[r] = 0.f;
        #pragma unroll
        for (int c = 0; c < 4; c++) o[r][c] = 0.f;
    }

    const float scale = 0.125f;   // 1/sqrt(64)

    for (int j = 0; j <= qt; j++) {
        __syncthreads();  // Qs ready (iter 0) / previous PV reads done

        // Load K^T and V tiles
        #pragma unroll
        for (int t = 0; t < 16; t++) {
            int e = tid + t * 256;
            int r = e >> 6, d = e & 63;
            size_t gi = base + (size_t)(j * 64 + r) * (3 * D_MODEL) + hcol + d;
            KtP[d * 65 + r] = g_qkv[gi + D_MODEL];
            Vs[r * 64 + d]  = g_qkv[gi + 2 * D_MODEL];
        }
        __syncthreads();

        // S = Q K^T
        float s[4][4];
        #pragma unroll
        for (int r = 0; r < 4; r++)
            #pragma unroll
            for (int c = 0; c < 4; c++) s[r][c] = 0.f;

        #pragma unroll 8
        for (int kk = 0; kk < 64; kk++) {
            float a[4], kb[4];
            #pragma unroll
            for (int r = 0; r < 4; r++) a[r] = Qs[(ty * 4 + r) * 64 + kk];
            #pragma unroll
            for (int c = 0; c < 4; c++) kb[c] = KtP[kk * 65 + tx * 4 + c];
            #pragma unroll
            for (int r = 0; r < 4; r++)
                #pragma unroll
                for (int c = 0; c < 4; c++) s[r][c] += a[r] * kb[c];
        }

        // scale + causal mask (only the diagonal tile needs it)
        #pragma unroll
        for (int r = 0; r < 4; r++)
            #pragma unroll
            for (int c = 0; c < 4; c++) {
                float v = s[r][c] * scale;
                if (j == qt && (tx * 4 + c) > (ty * 4 + r)) v = -1e30f;
                s[r][c] = v;
            }

        // online softmax update (reduce across the 16 tx-threads of each row)
        #pragma unroll
        for (int r = 0; r < 4; r++) {
            float rm = fmaxf(fmaxf(s[r][0], s[r][1]), fmaxf(s[r][2], s[r][3]));
            #pragma unroll
            for (int off = 8; off > 0; off >>= 1)
                rm = fmaxf(rm, __shfl_xor_sync(0xffffffffu, rm, off));
            float mnew  = fmaxf(m_i[r], rm);
            float alpha = __expf(m_i[r] - mnew);
            float rs = 0.f;
            #pragma unroll
            for (int c = 0; c < 4; c++) {
                s[r][c] = __expf(s[r][c] - mnew);
                rs += s[r][c];
            }
            #pragma unroll
            for (int off = 8; off > 0; off >>= 1)
                rs += __shfl_xor_sync(0xffffffffu, rs, off);
            l_i[r] = l_i[r] * alpha + rs;
            m_i[r] = mnew;
            #pragma unroll
            for (int c = 0; c < 4; c++) o[r][c] *= alpha;
        }

        __syncthreads();   // all Kt reads done -> safe to overwrite with P

        #pragma unroll
        for (int r = 0; r < 4; r++)
            #pragma unroll
            for (int c = 0; c < 4; c++)
                KtP[(ty * 4 + r) * 65 + tx * 4 + c] = s[r][c];
        __syncthreads();

        // O += P V
        #pragma unroll 8
        for (int kk = 0; kk < 64; kk++) {
            float pr[4];
            #pragma unroll
            for (int r = 0; r < 4; r++) pr[r] = KtP[(ty * 4 + r) * 65 + kk];
            float4 v4 = *(const float4*)&Vs[kk * 64 + tx * 4];
            float vv[4] = {v4.x, v4.y, v4.z, v4.w};
            #pragma unroll
            for (int r = 0; r < 4; r++)
                #pragma unroll
                for (int c = 0; c < 4; c++)
                    o[r][c] += pr[r] * vv[c];
        }
    }

    // finalize: y[b, t, h*64 + d] = o / l
    #pragma unroll
    for (int r = 0; r < 4; r++) {
        float inv = 1.f / l_i[r];
        float4 v = make_float4(o[r][0] * inv, o[r][1] * inv, o[r][2] * inv, o[r][3] * inv);
        size_t row = (size_t)(b * TT + qt * 64 + ty * 4 + r);
        *(float4*)&g_y[row * D_MODEL + hcol + tx * 4] = v;
    }
}

// ---------------------------------------------------------------------------
extern "C" void kernel_launch(void* const* d_in, const int* in_sizes, int n_in,
                              void* d_out, int out_size) {
    const float* x      = (const float*)d_in[0];
    const float* w_qkv  = (const float*)d_in[1];
    const float* w_proj = (const float*)d_in[2];
    float*       out    = (float*)d_out;

    float *qkv_ptr = nullptr, *y_ptr = nullptr;
    cudaGetSymbolAddress((void**)&qkv_ptr, g_qkv);
    cudaGetSymbolAddress((void**)&y_ptr,   g_y);

    cudaFuncSetAttribute(attn_flash, cudaFuncAttributeMaxDynamicSharedMemorySize, ATTN_SMEM);

    dim3 blk(256);

    // 1) qkv = x @ w_qkv^T : [8192,1024] x [3072,1024]^T -> [8192,3072]
    sgemm_nt<128, 128, 16, 8, 8>
        <<<dim3(3 * D_MODEL / 128, BT / 128), blk>>>(x, w_qkv, qkv_ptr,
                                                     BT, 3 * D_MODEL, D_MODEL);

    // 2) causal flash attention -> g_y [8192,1024]
    attn_flash<<<dim3(TT / 64, NH, BB), blk, ATTN_SMEM>>>();

    // 3) out = y @ w_proj^T : [8192,1024] x [1024,1024]^T -> [8192,1024]
    sgemm_nt<128, 128, 16, 8, 8>
        <<<dim3(D_MODEL / 128, BT / 128), blk>>>(y_ptr, w_proj, out,
                                                 BT, D_MODEL, D_MODEL);
}

// round 2
// speedup vs baseline: 1.5217x; 1.5217x over previous
#include <cuda_runtime.h>
#include <cstdint>
#include <cstddef>

#define D_MODEL 1024
#define NH      16
#define DH      64
#define BB      4
#define TT      2048
#define BT      (BB * TT)

// Scratch: device globals (no allocation allowed anywhere).
__device__ float g_qkv[(size_t)BT * 3 * D_MODEL];   // [B*T, 3072]
__device__ float g_y  [(size_t)BT * D_MODEL];       // [B*T, 1024]

// ---------------------------------------------------------------------------
// tf32 helpers
// ---------------------------------------------------------------------------
__device__ __forceinline__ uint32_t f2tf(float x) {
    uint32_t u;
    asm("cvt.rna.tf32.f32 %0, %1;" : "=r"(u) : "f"(x));
    return u;
}

__device__ __forceinline__ void mma_tf32(float c[4], const uint32_t a[4],
                                         const uint32_t b[2]) {
    asm volatile(
        "mma.sync.aligned.m16n8k8.row.col.f32.tf32.tf32.f32 "
        "{%0,%1,%2,%3},{%4,%5,%6,%7},{%8,%9},{%0,%1,%2,%3};"
        : "+f"(c[0]), "+f"(c[1]), "+f"(c[2]), "+f"(c[3])
        : "r"(a[0]), "r"(a[1]), "r"(a[2]), "r"(a[3]), "r"(b[0]), "r"(b[1]));
}

// ---------------------------------------------------------------------------
// TF32 tensor-core GEMM: C[M,N] = A[M,K] * B[N,K]^T
// Block tile 128x128, BK=32, 256 threads = 8 warps, warp tile 64x32.
// Smem holds tiles pre-permuted into mma fragment order:
//   A frag (m16n8k8): a0=[g][t], a1=[g+8][t], a2=[g][t+4], a3=[g+8][t+4]
//     (g=lane>>2, t=lane&3)  -> one LDS.128 per m-tile per k-step
//   B frag: b0=[k=t][n=g], b1=[t+4][g]       -> one LDS.64 per n-tile per k-step
// ---------------------------------------------------------------------------
__global__ __launch_bounds__(256)
void gemm_tf32(const float* __restrict__ A, const float* __restrict__ Bw,
               float* __restrict__ C, int M, int N, int K) {
    // As: [mtile(8)][kstep(4)][lane(32)][4]  = 4096 u32
    // Bs: [ntile(16)][kstep(4)][lane(32)][2] = 4096 u32
    __shared__ __align__(16) uint32_t As[8 * 4 * 32 * 4];
    __shared__ __align__(16) uint32_t Bs[16 * 4 * 32 * 2];

    const int tid    = threadIdx.x;
    const int lane   = tid & 31;
    const int wid    = tid >> 5;
    const int warp_m = wid >> 2;          // 0..1  (64 rows each)
    const int warp_n = wid & 3;           // 0..3  (32 cols each)
    const int m0     = blockIdx.y * 128;
    const int n0     = blockIdx.x * 128;

    float acc[4][4][4];
    #pragma unroll
    for (int i = 0; i < 4; i++)
        #pragma unroll
        for (int j = 0; j < 4; j++)
            #pragma unroll
            for (int r = 0; r < 4; r++) acc[i][j][r] = 0.f;

    for (int k0 = 0; k0 < K; k0 += 32) {
        // ---- stage A tile 128x32 (1024 float4, 4 per thread) ----
        #pragma unroll
        for (int it = 0; it < 4; it++) {
            int lin = tid + it * 256;
            int row = lin >> 3;          // 0..127 (m within tile)
            int kq  = lin & 7;           // which float4 in the 32-float row
            float4 v = *(const float4*)&A[(size_t)(m0 + row) * K + k0 + kq * 4];
            float e[4] = {v.x, v.y, v.z, v.w};
            int mtile = row >> 4, r = row & 15, g = r & 7, half = r >> 3;
            #pragma unroll
            for (int j = 0; j < 4; j++) {
                int k = kq * 4 + j, kstep = k >> 3, kc = k & 7;
                int lt  = g * 4 + (kc & 3);
                int idx = half + 2 * (kc >> 2);
                As[(((mtile * 4 + kstep) * 32) + lt) * 4 + idx] = f2tf(e[j]);
            }
        }
        // ---- stage B tile 128x32 ----
        #pragma unroll
        for (int it = 0; it < 4; it++) {
            int lin = tid + it * 256;
            int row = lin >> 3;          // n within tile
            int kq  = lin & 7;
            float4 v = *(const float4*)&Bw[(size_t)(n0 + row) * K + k0 + kq * 4];
            float e[4] = {v.x, v.y, v.z, v.w};
            int ntile = row >> 3, c = row & 7;
            #pragma unroll
            for (int j = 0; j < 4; j++) {
                int k = kq * 4 + j, kstep = k >> 3, kc = k & 7;
                int lt  = c * 4 + (kc & 3);
                int idx = kc >> 2;
                Bs[(((ntile * 4 + kstep) * 32) + lt) * 2 + idx] = f2tf(e[j]);
            }
        }
        __syncthreads();

        #pragma unroll
        for (int kstep = 0; kstep < 4; kstep++) {
            uint32_t af[4][4], bf[4][2];
            #pragma unroll
            for (int i = 0; i < 4; i++) {
                int mt = warp_m * 4 + i;
                uint4 v = *(const uint4*)&As[(((mt * 4 + kstep) * 32) + lane) * 4];
                af[i][0] = v.x; af[i][1] = v.y; af[i][2] = v.z; af[i][3] = v.w;
            }
            #pragma unroll
            for (int j = 0; j < 4; j++) {
                int nt = warp_n * 4 + j;
                uint2 v = *(const uint2*)&Bs[(((nt * 4 + kstep) * 32) + lane) * 2];
                bf[j][0] = v.x; bf[j][1] = v.y;
            }
            #pragma unroll
            for (int i = 0; i < 4; i++)
                #pragma unroll
                for (int j = 0; j < 4; j++)
                    mma_tf32(acc[i][j], af[i], bf[j]);
        }
        __syncthreads();
    }

    // ---- epilogue ----
    const int g = lane >> 2, t = lane & 3;
    #pragma unroll
    for (int i = 0; i < 4; i++) {
        int rbase = m0 + warp_m * 64 + i * 16 + g;
        #pragma unroll
        for (int j = 0; j < 4; j++) {
            int cbase = n0 + warp_n * 32 + j * 8 + t * 2;
            *(float2*)&C[(size_t)rbase * N + cbase] =
                make_float2(acc[i][j][0], acc[i][j][1]);
            *(float2*)&C[(size_t)(rbase + 8) * N + cbase] =
                make_float2(acc[i][j][2], acc[i][j][3]);
        }
    }
}

// ---------------------------------------------------------------------------
// Flash-style causal attention, fp32 (unchanged from round 1).
// ---------------------------------------------------------------------------
#define ATTN_SMEM ((64*64 + 64*65 + 64*64) * 4)

__global__ __launch_bounds__(256)
void attn_flash() {
    extern __shared__ __align__(16) float sm[];
    float* Qs  = sm;                       // [64][64]
    float* KtP = sm + 64 * 64;             // [64][65]
    float* Vs  = sm + 64 * 64 + 64 * 65;   // [64][64]

    const int tid = threadIdx.x;
    const int tx  = tid & 15;
    const int ty  = tid >> 4;
    const int qt  = blockIdx.x;
    const int h   = blockIdx.y;
    const int b   = blockIdx.z;

    const size_t base = (size_t)b * TT * (3 * D_MODEL);
    const int    hcol = h * DH;

    #pragma unroll
    for (int t = 0; t < 16; t++) {
        int e = tid + t * 256;
        int r = e >> 6, d = e & 63;
        Qs[r * 64 + d] = g_qkv[base + (size_t)(qt * 64 + r) * (3 * D_MODEL) + hcol + d];
    }

    float m_i[4], l_i[4], o[4][4];
    #pragma unroll
    for (int r = 0; r < 4; r++) {
        m_i[r] = -1e30f; l_i[r] = 0.f;
        #pragma unroll
        for (int c = 0; c < 4; c++) o[r][c] = 0.f;
    }

    const float scale = 0.125f;

    for (int j = 0; j <= qt; j++) {
        __syncthreads();

        #pragma unroll
        for (int t = 0; t < 16; t++) {
            int e = tid + t * 256;
            int r = e >> 6, d = e & 63;
            size_t gi = base + (size_t)(j * 64 + r) * (3 * D_MODEL) + hcol + d;
            KtP[d * 65 + r] = g_qkv[gi + D_MODEL];
            Vs[r * 64 + d]  = g_qkv[gi + 2 * D_MODEL];
        }
        __syncthreads();

        float s[4][4];
        #pragma unroll
        for (int r = 0; r < 4; r++)
            #pragma unroll
            for (int c = 0; c < 4; c++) s[r][c] = 0.f;

        #pragma unroll 8
        for (int kk = 0; kk < 64; kk++) {
            float a[4], kb[4];
            #pragma unroll
            for (int r = 0; r < 4; r++) a[r] = Qs[(ty * 4 + r) * 64 + kk];
            #pragma unroll
            for (int c = 0; c < 4; c++) kb[c] = KtP[kk * 65 + tx * 4 + c];
            #pragma unroll
            for (int r = 0; r < 4; r++)
                #pragma unroll
                for (int c = 0; c < 4; c++) s[r][c] += a[r] * kb[c];
        }

        #pragma unroll
        for (int r = 0; r < 4; r++)
            #pragma unroll
            for (int c = 0; c < 4; c++) {
                float v = s[r][c] * scale;
                if (j == qt && (tx * 4 + c) > (ty * 4 + r)) v = -1e30f;
                s[r][c] = v;
            }

        #pragma unroll
        for (int r = 0; r < 4; r++) {
            float rm = fmaxf(fmaxf(s[r][0], s[r][1]), fmaxf(s[r][2], s[r][3]));
            #pragma unroll
            for (int off = 8; off > 0; off >>= 1)
                rm = fmaxf(rm, __shfl_xor_sync(0xffffffffu, rm, off));
            float mnew  = fmaxf(m_i[r], rm);
            float alpha = __expf(m_i[r] - mnew);
            float rs = 0.f;
            #pragma unroll
            for (int c = 0; c < 4; c++) {
                s[r][c] = __expf(s[r][c] - mnew);
                rs += s[r][c];
            }
            #pragma unroll
            for (int off = 8; off > 0; off >>= 1)
                rs += __shfl_xor_sync(0xffffffffu, rs, off);
            l_i[r] = l_i[r] * alpha + rs;
            m_i[r] = mnew;
            #pragma unroll
            for (int c = 0; c < 4; c++) o[r][c] *= alpha;
        }

        __syncthreads();

        #pragma unroll
        for (int r = 0; r < 4; r++)
            #pragma unroll
            for (int c = 0; c < 4; c++)
                KtP[(ty * 4 + r) * 65 + tx * 4 + c] = s[r][c];
        __syncthreads();

        #pragma unroll 8
        for (int kk = 0; kk < 64; kk++) {
            float pr[4];
            #pragma unroll
            for (int r = 0; r < 4; r++) pr[r] = KtP[(ty * 4 + r) * 65 + kk];
            float4 v4 = *(const float4*)&Vs[kk * 64 + tx * 4];
            float vv[4] = {v4.x, v4.y, v4.z, v4.w};
            #pragma unroll
            for (int r = 0; r < 4; r++)
                #pragma unroll
                for (int c = 0; c < 4; c++)
                    o[r][c] += pr[r] * vv[c];
        }
    }

    #pragma unroll
    for (int r = 0; r < 4; r++) {
        float inv = 1.f / l_i[r];
        float4 v = make_float4(o[r][0] * inv, o[r][1] * inv, o[r][2] * inv, o[r][3] * inv);
        size_t row = (size_t)(b * TT + qt * 64 + ty * 4 + r);
        *(float4*)&g_y[row * D_MODEL + hcol + tx * 4] = v;
    }
}

// ---------------------------------------------------------------------------
extern "C" void kernel_launch(void* const* d_in, const int* in_sizes, int n_in,
                              void* d_out, int out_size) {
    const float* x      = (const float*)d_in[0];
    const float* w_qkv  = (const float*)d_in[1];
    const float* w_proj = (const float*)d_in[2];
    float*       out    = (float*)d_out;

    float *qkv_ptr = nullptr, *y_ptr = nullptr;
    cudaGetSymbolAddress((void**)&qkv_ptr, g_qkv);
    cudaGetSymbolAddress((void**)&y_ptr,   g_y);

    cudaFuncSetAttribute(attn_flash, cudaFuncAttributeMaxDynamicSharedMemorySize, ATTN_SMEM);

    dim3 blk(256);

    // 1) qkv = x @ w_qkv^T : [8192,1024] x [3072,1024]^T -> [8192,3072]
    gemm_tf32<<<dim3(3 * D_MODEL / 128, BT / 128), blk>>>(x, w_qkv, qkv_ptr,
                                                          BT, 3 * D_MODEL, D_MODEL);

    // 2) causal flash attention -> g_y [8192,1024]
    attn_flash<<<dim3(TT / 64, NH, BB), blk, ATTN_SMEM>>>();

    // 3) out = y @ w_proj^T : [8192,1024] x [1024,1024]^T -> [8192,1024]
    gemm_tf32<<<dim3(D_MODEL / 128, BT / 128), blk>>>(y_ptr, w_proj, out,
                                                      BT, D_MODEL, D_MODEL);
}

// round 3
// speedup vs baseline: 1.8299x; 1.2025x over previous
#include <cuda_runtime.h>
#include <cstdint>
#include <cstddef>

#define D_MODEL 1024
#define NH      16
#define DH      64
#define BB      4
#define TT      2048
#define BT      (BB * TT)

__device__ float g_qkv[(size_t)BT * 3 * D_MODEL];   // [B*T, 3072]
__device__ float g_y  [(size_t)BT * D_MODEL];       // [B*T, 1024]

// ---------------------------------------------------------------------------
__device__ __forceinline__ uint32_t f2tf(float x) {
    uint32_t u;
    asm("cvt.rna.tf32.f32 %0, %1;" : "=r"(u) : "f"(x));
    return u;
}

__device__ __forceinline__ void mma_tf32(float c[4], const uint32_t a[4],
                                         const uint32_t b[2]) {
    asm volatile(
        "mma.sync.aligned.m16n8k8.row.col.f32.tf32.tf32.f32 "
        "{%0,%1,%2,%3},{%4,%5,%6,%7},{%8,%9},{%0,%1,%2,%3};"
        : "+f"(c[0]), "+f"(c[1]), "+f"(c[2]), "+f"(c[3])
        : "r"(a[0]), "r"(a[1]), "r"(a[2]), "r"(a[3]), "r"(b[0]), "r"(b[1]));
}

// ---------------------------------------------------------------------------
// TF32 GEMM v3: C[M,N] = A[M,K] * B[N,K]^T, conflict-free fragment staging.
// As layout: [mtile 8][kstep 4][aidx 4][lane 32]
// Bs layout: [ntile 16][kstep 4][plane 2][lane 32]
// Fragment semantics (validated round 2):
//   a0=[g][t] a1=[g+8][t] a2=[g][t+4] a3=[g+8][t+4]; b0=[n=g][k=t] b1=[g][t+4]
// ---------------------------------------------------------------------------
__global__ __launch_bounds__(256)
void gemm_tf32(const float* __restrict__ A, const float* __restrict__ Bw,
               float* __restrict__ C, int M, int N, int K) {
    __shared__ __align__(16) uint32_t As[8 * 4 * 4 * 32];
    __shared__ __align__(16) uint32_t Bs[16 * 4 * 2 * 32];

    const int tid    = threadIdx.x;
    const int lane   = tid & 31;
    const int wid    = tid >> 5;
    const int warp_m = wid >> 2;
    const int warp_n = wid & 3;
    const int m0     = blockIdx.y * 128;
    const int n0     = blockIdx.x * 128;

    float acc[4][4][4];
    #pragma unroll
    for (int i = 0; i < 4; i++)
        #pragma unroll
        for (int j = 0; j < 4; j++)
            #pragma unroll
            for (int r = 0; r < 4; r++) acc[i][j][r] = 0.f;

    for (int k0 = 0; k0 < K; k0 += 32) {
        // ---- stage A: warp covers 8 rows x 4 k-quads -> STS.128 contiguous ----
        #pragma unroll
        for (int it = 0; it < 4; it++) {
            int lin = tid + it * 256;
            int row = (lin & 7) | ((lin >> 6) << 3);   // 0..127
            int c   = (lin >> 3) & 7;                  // k-quad 0..7
            float4 v = *(const float4*)&A[(size_t)(m0 + row) * K + k0 + c * 4];
            int aidx = ((row >> 3) & 1) + 2 * (c & 1);
            int off  = (((((row >> 4) * 4 + (c >> 1)) * 4) + aidx) << 5) + ((row & 7) << 2);
            *(uint4*)&As[off] = make_uint4(f2tf(v.x), f2tf(v.y), f2tf(v.z), f2tf(v.w));
        }
        // ---- stage B ----
        #pragma unroll
        for (int it = 0; it < 4; it++) {
            int lin = tid + it * 256;
            int row = (lin & 7) | ((lin >> 6) << 3);
            int c   = (lin >> 3) & 7;
            float4 v = *(const float4*)&Bw[(size_t)(n0 + row) * K + k0 + c * 4];
            int off = (((((row >> 3) * 4 + (c >> 1)) * 2) + (c & 1)) << 5) + ((row & 7) << 2);
            *(uint4*)&Bs[off] = make_uint4(f2tf(v.x), f2tf(v.y), f2tf(v.z), f2tf(v.w));
        }
        __syncthreads();

        #pragma unroll
        for (int ks = 0; ks < 4; ks++) {
            uint32_t af[4][4], bf[4][2];
            #pragma unroll
            for (int i = 0; i < 4; i++) {
                int base = ((warp_m * 4 + i) * 4 + ks) * 4 * 32;
                af[i][0] = As[base + lane];
                af[i][1] = As[base + 32 + lane];
                af[i][2] = As[base + 64 + lane];
                af[i][3] = As[base + 96 + lane];
            }
            #pragma unroll
            for (int j = 0; j < 4; j++) {
                int base = ((warp_n * 4 + j) * 4 + ks) * 2 * 32;
                bf[j][0] = Bs[base + lane];
                bf[j][1] = Bs[base + 32 + lane];
            }
            #pragma unroll
            for (int i = 0; i < 4; i++)
                #pragma unroll
                for (int j = 0; j < 4; j++)
                    mma_tf32(acc[i][j], af[i], bf[j]);
        }
        __syncthreads();
    }

    const int g = lane >> 2, t = lane & 3;
    #pragma unroll
    for (int i = 0; i < 4; i++) {
        int rbase = m0 + warp_m * 64 + i * 16 + g;
        #pragma unroll
        for (int j = 0; j < 4; j++) {
            int cbase = n0 + warp_n * 32 + j * 8 + t * 2;
            *(float2*)&C[(size_t)rbase * N + cbase] =
                make_float2(acc[i][j][0], acc[i][j][1]);
            *(float2*)&C[(size_t)(rbase + 8) * N + cbase] =
                make_float2(acc[i][j][2], acc[i][j][3]);
        }
    }
}

// ---------------------------------------------------------------------------
// Tensor-core flash attention (tf32).
// Block = 128 thr = 4 warps; warp w owns 16 queries. 64-key tiles.
// Kf: [kg_d 8][nt_key 8][plane 2][lane 32]   (B-frag for S = Q K^T)
// Vf: [kg_key 8][nt_d 8][plane 2][lane^swz]  (B-frag for O = P V), swz = 4(nt&1)^8p
// Q fragments kept in registers for whole kernel; P C-layout -> A-layout via shfl.
// ---------------------------------------------------------------------------
__global__ __launch_bounds__(128)
void attn_tc() {
    __shared__ __align__(16) uint32_t Kf[8 * 8 * 2 * 32];
    __shared__ __align__(16) uint32_t Vf[8 * 8 * 2 * 32];

    const int tid  = threadIdx.x;
    const int lane = tid & 31;
    const int w    = tid >> 5;
    const int g    = lane >> 2;
    const int t    = lane & 3;
    const int qt   = blockIdx.x;
    const int h    = blockIdx.y;
    const int b    = blockIdx.z;

    const size_t base = (size_t)b * TT * (3 * D_MODEL);
    const int    hcol = h * DH;
    const int    q0   = qt * 64 + w * 16;

    // Q fragments (tf32) in registers: qf[kg][0..3]
    uint32_t qf[8][4];
    {
        const float* qA = g_qkv + base + (size_t)(q0 + g) * (3 * D_MODEL) + hcol;
        const float* qB = qA + (size_t)8 * (3 * D_MODEL);
        #pragma unroll
        for (int kg = 0; kg < 8; kg++) {
            qf[kg][0] = f2tf(qA[kg * 8 + t]);
            qf[kg][1] = f2tf(qB[kg * 8 + t]);
            qf[kg][2] = f2tf(qA[kg * 8 + t + 4]);
            qf[kg][3] = f2tf(qB[kg * 8 + t + 4]);
        }
    }

    float m0v = -1e30f, m1v = -1e30f, l0 = 0.f, l1 = 0.f;
    float o[8][4];
    #pragma unroll
    for (int nt = 0; nt < 8; nt++)
        #pragma unroll
        for (int e = 0; e < 4; e++) o[nt][e] = 0.f;

    const int src  = (lane & ~3) | (t >> 1);
    const int src2 = src + 2;

    for (int j = 0; j <= qt; j++) {
        __syncthreads();
        // ---- stage K, V tiles (64 keys x 64 d) ----
        #pragma unroll
        for (int it = 0; it < 8; it++) {
            int lin = tid + it * 128;
            int key = (lin & 7) | ((lin >> 7) << 3);   // 0..63
            int c   = (lin >> 3) & 15;                 // float4 index 0..15
            const float* kvp = g_qkv + base + (size_t)(j * 64 + key) * (3 * D_MODEL)
                               + D_MODEL + hcol + c * 4;
            float4 kv4 = *(const float4*)kvp;
            float4 vv4 = *(const float4*)(kvp + D_MODEL);

            // K: frag (kg=d>>3, nt=key>>3), lane-contiguous STS.128
            int koff = (((((c >> 1) * 8 + (key >> 3)) * 2) + (c & 1)) << 5) + ((key & 7) << 2);
            *(uint4*)&Kf[koff] = make_uint4(f2tf(kv4.x), f2tf(kv4.y), f2tf(kv4.z), f2tf(kv4.w));

            // V transpose: frag (kg=key>>3, nt=d>>3), swizzled scatter STS.32 x4
            int kgv  = key >> 3;
            int pv   = (key >> 2) & 1;
            int ntv  = c >> 1;
            int vb   = ((kgv * 8 + ntv) * 2 + pv) << 5;
            int lb   = 16 * (c & 1) + (key & 3);
            int swz  = (4 * (ntv & 1)) ^ (8 * pv);
            float ve[4] = {vv4.x, vv4.y, vv4.z, vv4.w};
            #pragma unroll
            for (int jj = 0; jj < 4; jj++)
                Vf[vb + ((lb + 4 * jj) ^ swz)] = f2tf(ve[jj]);
        }
        __syncthreads();

        const int lim = (j == qt) ? (2 * w + 2) : 8;

        // ---- S = Q K^T ----
        float s[8][4];
        #pragma unroll
        for (int nt = 0; nt < 8; nt++) {
            if (nt < lim) {
                #pragma unroll
                for (int e = 0; e < 4; e++) s[nt][e] = 0.f;
                #pragma unroll
                for (int kg = 0; kg < 8; kg++) {
                    int kb = ((kg * 8 + nt) * 2) << 5;
                    uint32_t bf[2] = {Kf[kb + lane], Kf[kb + 32 + lane]};
                    mma_tf32(s[nt], qf[kg], bf);
                }
            }
        }

        // ---- scale + causal mask ----
        #pragma unroll
        for (int nt = 0; nt < 8; nt++) {
            if (nt < lim) {
                #pragma unroll
                for (int e = 0; e < 4; e++) {
                    float v = s[nt][e] * 0.125f;
                    if (j == qt) {
                        int keyl = nt * 8 + 2 * t + (e & 1);
                        int rowl = w * 16 + g + ((e >> 1) << 3);
                        if (keyl > rowl) v = -1e30f;
                    }
                    s[nt][e] = v;
                }
            }
        }

        // ---- online softmax ----
        float rm0 = -1e30f, rm1 = -1e30f;
        #pragma unroll
        for (int nt = 0; nt < 8; nt++) {
            if (nt < lim) {
                rm0 = fmaxf(rm0, fmaxf(s[nt][0], s[nt][1]));
                rm1 = fmaxf(rm1, fmaxf(s[nt][2], s[nt][3]));
            }
        }
        rm0 = fmaxf(rm0, __shfl_xor_sync(0xffffffffu, rm0, 1));
        rm0 = fmaxf(rm0, __shfl_xor_sync(0xffffffffu, rm0, 2));
        rm1 = fmaxf(rm1, __shfl_xor_sync(0xffffffffu, rm1, 1));
        rm1 = fmaxf(rm1, __shfl_xor_sync(0xffffffffu, rm1, 2));

        float mn0 = fmaxf(m0v, rm0), mn1 = fmaxf(m1v, rm1);
        float a0 = __expf(m0v - mn0), a1 = __expf(m1v - mn1);
        m0v = mn0; m1v = mn1;

        float rs0 = 0.f, rs1 = 0.f;
        #pragma unroll
        for (int nt = 0; nt < 8; nt++) {
            if (nt < lim) {
                s[nt][0] = __expf(s[nt][0] - mn0);
                s[nt][1] = __expf(s[nt][1] - mn0);
                s[nt][2] = __expf(s[nt][2] - mn1);
                s[nt][3] = __expf(s[nt][3] - mn1);
                rs0 += s[nt][0] + s[nt][1];
                rs1 += s[nt][2] + s[nt][3];
            }
        }
        rs0 += __shfl_xor_sync(0xffffffffu, rs0, 1);
        rs0 += __shfl_xor_sync(0xffffffffu, rs0, 2);
        rs1 += __shfl_xor_sync(0xffffffffu, rs1, 1);
        rs1 += __shfl_xor_sync(0xffffffffu, rs1, 2);
        l0 = l0 * a0 + rs0;
        l1 = l1 * a1 + rs1;

        #pragma unroll
        for (int nt = 0; nt < 8; nt++) {
            o[nt][0] *= a0; o[nt][1] *= a0;
            o[nt][2] *= a1; o[nt][3] *= a1;
        }

        // ---- P: cvt + C-layout -> A-layout via shfl (in place) ----
        uint32_t p[8][4];
        #pragma unroll
        for (int kg = 0; kg < 8; kg++) {
            if (kg < lim) {
                uint32_t c0 = f2tf(s[kg][0]), c1 = f2tf(s[kg][1]);
                uint32_t c2 = f2tf(s[kg][2]), c3 = f2tf(s[kg][3]);
                uint32_t u0 = __shfl_sync(0xffffffffu, c0, src);
                uint32_t u1 = __shfl_sync(0xffffffffu, c1, src);
                uint32_t u2 = __shfl_sync(0xffffffffu, c2, src);
                uint32_t u3 = __shfl_sync(0xffffffffu, c3, src);
                uint32_t v0 = __shfl_sync(0xffffffffu, c0, src2);
                uint32_t v1 = __shfl_sync(0xffffffffu, c1, src2);
                uint32_t v2 = __shfl_sync(0xffffffffu, c2, src2);
                uint32_t v3 = __shfl_sync(0xffffffffu, c3, src2);
                bool odd = (t & 1);
                p[kg][0] = odd ? u1 : u0;   // P[g][8kg+t]
                p[kg][1] = odd ? u3 : u2;   // P[g+8][8kg+t]
                p[kg][2] = odd ? v1 : v0;   // P[g][8kg+t+4]
                p[kg][3] = odd ? v3 : v2;   // P[g+8][8kg+t+4]
            }
        }

        // ---- O += P V ----
        #pragma unroll
        for (int nt = 0; nt < 8; nt++) {          // d groups
            int sw0 = 4 * (nt & 1);
            #pragma unroll
            for (int kg = 0; kg < 8; kg++) {      // key groups
                if (kg < lim) {
                    int vb = ((kg * 8 + nt) * 2) << 5;
                    uint32_t bf[2] = {Vf[vb + (lane ^ sw0)],
                                      Vf[vb + 32 + (lane ^ sw0 ^ 8)]};
                    mma_tf32(o[nt], p[kg], bf);
                }
            }
        }
    }

    // ---- epilogue ----
    float inv0 = 1.f / l0, inv1 = 1.f / l1;
    size_t r0 = (size_t)(b * TT + q0 + g) * D_MODEL + hcol;
    size_t r1 = (size_t)(b * TT + q0 + g + 8) * D_MODEL + hcol;
    #pragma unroll
    for (int nt = 0; nt < 8; nt++) {
        int cb = nt * 8 + 2 * t;
        *(float2*)&g_y[r0 + cb] = make_float2(o[nt][0] * inv0, o[nt][1] * inv0);
        *(float2*)&g_y[r1 + cb] = make_float2(o[nt][2] * inv1, o[nt][3] * inv1);
    }
}

// ---------------------------------------------------------------------------
extern "C" void kernel_launch(void* const* d_in, const int* in_sizes, int n_in,
                              void* d_out, int out_size) {
    const float* x      = (const float*)d_in[0];
    const float* w_qkv  = (const float*)d_in[1];
    const float* w_proj = (const float*)d_in[2];
    float*       out    = (float*)d_out;

    float *qkv_ptr = nullptr, *y_ptr = nullptr;
    cudaGetSymbolAddress((void**)&qkv_ptr, g_qkv);
    cudaGetSymbolAddress((void**)&y_ptr,   g_y);

    gemm_tf32<<<dim3(3 * D_MODEL / 128, BT / 128), 256>>>(x, w_qkv, qkv_ptr,
                                                          BT, 3 * D_MODEL, D_MODEL);

    attn_tc<<<dim3(TT / 64, NH, BB), 128>>>();

    gemm_tf32<<<dim3(D_MODEL / 128, BT / 128), 256>>>(y_ptr, w_proj, out,
                                                      BT, D_MODEL, D_MODEL);
}

// round 5
// speedup vs baseline: 2.6313x; 1.4380x over previous
#include <cuda_runtime.h>
#include <cstdint>
#include <cstddef>

#define D_MODEL 1024
#define NH      16
#define DH      64
#define BB      4
#define TT      2048
#define BT      (BB * TT)

__device__ float g_qkv[(size_t)BT * 3 * D_MODEL];   // [B*T, 3072]
__device__ float g_y  [(size_t)BT * D_MODEL];       // [B*T, 1024]

// ---------------------------------------------------------------------------
__device__ __forceinline__ uint32_t f2tf(float x) {
    uint32_t u;
    asm("cvt.rna.tf32.f32 %0, %1;" : "=r"(u) : "f"(x));
    return u;
}

__device__ __forceinline__ void mma_tf32(float c[4], const uint32_t a[4],
                                         const uint32_t b[2]) {
    asm volatile(
        "mma.sync.aligned.m16n8k8.row.col.f32.tf32.tf32.f32 "
        "{%0,%1,%2,%3},{%4,%5,%6,%7},{%8,%9},{%0,%1,%2,%3};"
        : "+f"(c[0]), "+f"(c[1]), "+f"(c[2]), "+f"(c[3])
        : "r"(a[0]), "r"(a[1]), "r"(a[2]), "r"(a[3]), "r"(b[0]), "r"(b[1]));
}

// ---------------------------------------------------------------------------
// TF32 GEMM v4: C[M,N] = A[M,K] * B[N,K]^T.
// Coalesced LDG (8 lanes per 128B row) + XOR-swizzled fragment-order smem
// (conflict-free STS.128 and LDS.32).
//   As: [mtile 8][kstep 4][aidx 4][pos 32]  pos = (4*(row&7)+j) ^ 4q
//   Bs: [ntile 16][kstep 4][plane 2][pos 32]
// Fragment semantics (validated round 2):
//   a0=[g][t] a1=[g+8][t] a2=[g][t+4] a3=[g+8][t+4]; b0=[n=g][k=t] b1=[g][t+4]
// ---------------------------------------------------------------------------
__global__ __launch_bounds__(256)
void gemm_tf32(const float* __restrict__ A, const float* __restrict__ Bw,
               float* __restrict__ C, int M, int N, int K) {
    __shared__ __align__(16) uint32_t As[8 * 4 * 4 * 32];
    __shared__ __align__(16) uint32_t Bs[16 * 4 * 2 * 32];

    const int tid    = threadIdx.x;
    const int lane   = tid & 31;
    const int wid    = tid >> 5;
    const int warp_m = wid >> 2;
    const int warp_n = wid & 3;
    const int m0     = blockIdx.y * 128;
    const int n0     = blockIdx.x * 128;

    float acc[4][4][4];
    #pragma unroll
    for (int i = 0; i < 4; i++)
        #pragma unroll
        for (int j = 0; j < 4; j++)
            #pragma unroll
            for (int r = 0; r < 4; r++) acc[i][j][r] = 0.f;

    for (int k0 = 0; k0 < K; k0 += 32) {
        // ---- stage A (coalesced LDG.128, swizzled STS.128) ----
        #pragma unroll
        for (int it = 0; it < 4; it++) {
            int lin = tid + it * 256;
            int row = lin >> 3;                 // 0..127
            int q   = lin & 7;                  // k-quad
            float4 v = *(const float4*)&A[(size_t)(m0 + row) * K + k0 + q * 4];
            int mtile = row >> 4;
            int kstep = q >> 1;
            int aidx  = ((row >> 3) & 1) + 2 * (q & 1);
            int pos   = (((row & 7) << 2)) ^ (q << 2);
            int off   = (((mtile * 4 + kstep) * 4 + aidx) << 5) + pos;
            *(uint4*)&As[off] = make_uint4(f2tf(v.x), f2tf(v.y), f2tf(v.z), f2tf(v.w));
        }
        // ---- stage B ----
        #pragma unroll
        for (int it = 0; it < 4; it++) {
            int lin = tid + it * 256;
            int row = lin >> 3;
            int q   = lin & 7;
            float4 v = *(const float4*)&Bw[(size_t)(n0 + row) * K + k0 + q * 4];
            int ntile = row >> 3;
            int kstep = q >> 1;
            int plane = q & 1;
            int pos   = (((row & 7) << 2)) ^ (q << 2);
            int off   = (((ntile * 4 + kstep) * 2 + plane) << 5) + pos;
            *(uint4*)&Bs[off] = make_uint4(f2tf(v.x), f2tf(v.y), f2tf(v.z), f2tf(v.w));
        }
        __syncthreads();

        #pragma unroll
        for (int ks = 0; ks < 4; ks++) {
            uint32_t af[4][4], bf[4][2];
            #pragma unroll
            for (int i = 0; i < 4; i++) {
                int base = ((warp_m * 4 + i) * 4 + ks) * 4 * 32;
                #pragma unroll
                for (int aidx = 0; aidx < 4; aidx++) {
                    int q = 2 * ks + (aidx >> 1);
                    af[i][aidx] = As[base + aidx * 32 + (lane ^ (q << 2))];
                }
            }
            #pragma unroll
            for (int j = 0; j < 4; j++) {
                int base = ((warp_n * 4 + j) * 4 + ks) * 2 * 32;
                #pragma unroll
                for (int p = 0; p < 2; p++) {
                    int q = 2 * ks + p;
                    bf[j][p] = Bs[base + p * 32 + (lane ^ (q << 2))];
                }
            }
            #pragma unroll
            for (int i = 0; i < 4; i++)
                #pragma unroll
                for (int j = 0; j < 4; j++)
                    mma_tf32(acc[i][j], af[i], bf[j]);
        }
        __syncthreads();
    }

    const int g = lane >> 2, t = lane & 3;
    #pragma unroll
    for (int i = 0; i < 4; i++) {
        int rbase = m0 + warp_m * 64 + i * 16 + g;
        #pragma unroll
        for (int j = 0; j < 4; j++) {
            int cbase = n0 + warp_n * 32 + j * 8 + t * 2;
            *(float2*)&C[(size_t)rbase * N + cbase] =
                make_float2(acc[i][j][0], acc[i][j][1]);
            *(float2*)&C[(size_t)(rbase + 8) * N + cbase] =
                make_float2(acc[i][j][2], acc[i][j][3]);
        }
    }
}

// ---------------------------------------------------------------------------
// Tensor-core flash attention (tf32, mma.sync) — unchanged from round 3.
// ---------------------------------------------------------------------------
__global__ __launch_bounds__(128)
void attn_tc() {
    __shared__ __align__(16) uint32_t Kf[8 * 8 * 2 * 32];
    __shared__ __align__(16) uint32_t Vf[8 * 8 * 2 * 32];

    const int tid  = threadIdx.x;
    const int lane = tid & 31;
    const int w    = tid >> 5;
    const int g    = lane >> 2;
    const int t    = lane & 3;
    const int qt   = blockIdx.x;
    const int h    = blockIdx.y;
    const int b    = blockIdx.z;

    const size_t base = (size_t)b * TT * (3 * D_MODEL);
    const int    hcol = h * DH;
    const int    q0   = qt * 64 + w * 16;

    uint32_t qf[8][4];
    {
        const float* qA = g_qkv + base + (size_t)(q0 + g) * (3 * D_MODEL) + hcol;
        const float* qB = qA + (size_t)8 * (3 * D_MODEL);
        #pragma unroll
        for (int kg = 0; kg < 8; kg++) {
            qf[kg][0] = f2tf(qA[kg * 8 + t]);
            qf[kg][1] = f2tf(qB[kg * 8 + t]);
            qf[kg][2] = f2tf(qA[kg * 8 + t + 4]);
            qf[kg][3] = f2tf(qB[kg * 8 + t + 4]);
        }
    }

    float m0v = -1e30f, m1v = -1e30f, l0 = 0.f, l1 = 0.f;
    float o[8][4];
    #pragma unroll
    for (int nt = 0; nt < 8; nt++)
        #pragma unroll
        for (int e = 0; e < 4; e++) o[nt][e] = 0.f;

    const int src  = (lane & ~3) | (t >> 1);
    const int src2 = src + 2;

    for (int j = 0; j <= qt; j++) {
        __syncthreads();
        #pragma unroll
        for (int it = 0; it < 8; it++) {
            int lin = tid + it * 128;
            int key = (lin & 7) | ((lin >> 7) << 3);
            int c   = (lin >> 3) & 15;
            const float* kvp = g_qkv + base + (size_t)(j * 64 + key) * (3 * D_MODEL)
                               + D_MODEL + hcol + c * 4;
            float4 kv4 = *(const float4*)kvp;
            float4 vv4 = *(const float4*)(kvp + D_MODEL);

            int koff = (((((c >> 1) * 8 + (key >> 3)) * 2) + (c & 1)) << 5) + ((key & 7) << 2);
            *(uint4*)&Kf[koff] = make_uint4(f2tf(kv4.x), f2tf(kv4.y), f2tf(kv4.z), f2tf(kv4.w));

            int kgv  = key >> 3;
            int pv   = (key >> 2) & 1;
            int ntv  = c >> 1;
            int vb   = ((kgv * 8 + ntv) * 2 + pv) << 5;
            int lb   = 16 * (c & 1) + (key & 3);
            int swz  = (4 * (ntv & 1)) ^ (8 * pv);
            float ve[4] = {vv4.x, vv4.y, vv4.z, vv4.w};
            #pragma unroll
            for (int jj = 0; jj < 4; jj++)
                Vf[vb + ((lb + 4 * jj) ^ swz)] = f2tf(ve[jj]);
        }
        __syncthreads();

        const int lim = (j == qt) ? (2 * w + 2) : 8;

        float s[8][4];
        #pragma unroll
        for (int nt = 0; nt < 8; nt++) {
            if (nt < lim) {
                #pragma unroll
                for (int e = 0; e < 4; e++) s[nt][e] = 0.f;
                #pragma unroll
                for (int kg = 0; kg < 8; kg++) {
                    int kb = ((kg * 8 + nt) * 2) << 5;
                    uint32_t bf[2] = {Kf[kb + lane], Kf[kb + 32 + lane]};
                    mma_tf32(s[nt], qf[kg], bf);
                }
            }
        }

        #pragma unroll
        for (int nt = 0; nt < 8; nt++) {
            if (nt < lim) {
                #pragma unroll
                for (int e = 0; e < 4; e++) {
                    float v = s[nt][e] * 0.125f;
                    if (j == qt) {
                        int keyl = nt * 8 + 2 * t + (e & 1);
                        int rowl = w * 16 + g + ((e >> 1) << 3);
                        if (keyl > rowl) v = -1e30f;
                    }
                    s[nt][e] = v;
                }
            }
        }

        float rm0 = -1e30f, rm1 = -1e30f;
        #pragma unroll
        for (int nt = 0; nt < 8; nt++) {
            if (nt < lim) {
                rm0 = fmaxf(rm0, fmaxf(s[nt][0], s[nt][1]));
                rm1 = fmaxf(rm1, fmaxf(s[nt][2], s[nt][3]));
            }
        }
        rm0 = fmaxf(rm0, __shfl_xor_sync(0xffffffffu, rm0, 1));
        rm0 = fmaxf(rm0, __shfl_xor_sync(0xffffffffu, rm0, 2));
        rm1 = fmaxf(rm1, __shfl_xor_sync(0xffffffffu, rm1, 1));
        rm1 = fmaxf(rm1, __shfl_xor_sync(0xffffffffu, rm1, 2));

        float mn0 = fmaxf(m0v, rm0), mn1 = fmaxf(m1v, rm1);
        float a0 = __expf(m0v - mn0), a1 = __expf(m1v - mn1);
        m0v = mn0; m1v = mn1;

        float rs0 = 0.f, rs1 = 0.f;
        #pragma unroll
        for (int nt = 0; nt < 8; nt++) {
            if (nt < lim) {
                s[nt][0] = __expf(s[nt][0] - mn0);
                s[nt][1] = __expf(s[nt][1] - mn0);
                s[nt][2] = __expf(s[nt][2] - mn1);
                s[nt][3] = __expf(s[nt][3] - mn1);
                rs0 += s[nt][0] + s[nt][1];
                rs1 += s[nt][2] + s[nt][3];
            }
        }
        rs0 += __shfl_xor_sync(0xffffffffu, rs0, 1);
        rs0 += __shfl_xor_sync(0xffffffffu, rs0, 2);
        rs1 += __shfl_xor_sync(0xffffffffu, rs1, 1);
        rs1 += __shfl_xor_sync(0xffffffffu, rs1, 2);
        l0 = l0 * a0 + rs0;
        l1 = l1 * a1 + rs1;

        #pragma unroll
        for (int nt = 0; nt < 8; nt++) {
            o[nt][0] *= a0; o[nt][1] *= a0;
            o[nt][2] *= a1; o[nt][3] *= a1;
        }

        uint32_t p[8][4];
        #pragma unroll
        for (int kg = 0; kg < 8; kg++) {
            if (kg < lim) {
                uint32_t c0 = f2tf(s[kg][0]), c1 = f2tf(s[kg][1]);
                uint32_t c2 = f2tf(s[kg][2]), c3 = f2tf(s[kg][3]);
                uint32_t u0 = __shfl_sync(0xffffffffu, c0, src);
                uint32_t u1 = __shfl_sync(0xffffffffu, c1, src);
                uint32_t u2 = __shfl_sync(0xffffffffu, c2, src);
                uint32_t u3 = __shfl_sync(0xffffffffu, c3, src);
                uint32_t v0 = __shfl_sync(0xffffffffu, c0, src2);
                uint32_t v1 = __shfl_sync(0xffffffffu, c1, src2);
                uint32_t v2 = __shfl_sync(0xffffffffu, c2, src2);
                uint32_t v3 = __shfl_sync(0xffffffffu, c3, src2);
                bool odd = (t & 1);
                p[kg][0] = odd ? u1 : u0;
                p[kg][1] = odd ? u3 : u2;
                p[kg][2] = odd ? v1 : v0;
                p[kg][3] = odd ? v3 : v2;
            }
        }

        #pragma unroll
        for (int nt = 0; nt < 8; nt++) {
            int sw0 = 4 * (nt & 1);
            #pragma unroll
            for (int kg = 0; kg < 8; kg++) {
                if (kg < lim) {
                    int vb = ((kg * 8 + nt) * 2) << 5;
                    uint32_t bf[2] = {Vf[vb + (lane ^ sw0)],
                                      Vf[vb + 32 + (lane ^ sw0 ^ 8)]};
                    mma_tf32(o[nt], p[kg], bf);
                }
            }
        }
    }

    float inv0 = 1.f / l0, inv1 = 1.f / l1;
    size_t r0 = (size_t)(b * TT + q0 + g) * D_MODEL + hcol;
    size_t r1 = (size_t)(b * TT + q0 + g + 8) * D_MODEL + hcol;
    #pragma unroll
    for (int nt = 0; nt < 8; nt++) {
        int cb = nt * 8 + 2 * t;
        *(float2*)&g_y[r0 + cb] = make_float2(o[nt][0] * inv0, o[nt][1] * inv0);
        *(float2*)&g_y[r1 + cb] = make_float2(o[nt][2] * inv1, o[nt][3] * inv1);
    }
}

// ---------------------------------------------------------------------------
extern "C" void kernel_launch(void* const* d_in, const int* in_sizes, int n_in,
                              void* d_out, int out_size) {
    const float* x      = (const float*)d_in[0];
    const float* w_qkv  = (const float*)d_in[1];
    const float* w_proj = (const float*)d_in[2];
    float*       out    = (float*)d_out;

    float *qkv_ptr = nullptr, *y_ptr = nullptr;
    cudaGetSymbolAddress((void**)&qkv_ptr, g_qkv);
    cudaGetSymbolAddress((void**)&y_ptr,   g_y);

    gemm_tf32<<<dim3(3 * D_MODEL / 128, BT / 128), 256>>>(x, w_qkv, qkv_ptr,
                                                          BT, 3 * D_MODEL, D_MODEL);

    attn_tc<<<dim3(TT / 64, NH, BB), 128>>>();

    gemm_tf32<<<dim3(D_MODEL / 128, BT / 128), 256>>>(y_ptr, w_proj, out,
                                                      BT, D_MODEL, D_MODEL);
}